// round 14
// baseline (speedup 1.0000x reference)
#include <cuda_runtime.h>
#include <cuda_fp16.h>
#include <math.h>
#include <stdint.h>

#define D_MODEL   4096
#define NE        64
#define NTOK_MAX  32768
#define TAU       5e-3f   // certification margin (~12.5 sigma of fp16 screen noise)
#define WIN       5e-3f   // candidate-containment window for rescued tokens

// ---------------- scratch (__device__ globals: allocation-free) ----------------
// W permuted into warp-contiguous HMMA B-fragment blocks (R11-proven layout):
// block (nt, ks2) = 512B; lane l = rsub*4+q (expert e = nt*8+rsub) holds uint4 =
//   { half2(W[e][32ks2+2q],+1), half2(W[e][32ks2+8+2q],+1),
//     half2(W[e][32ks2+16+2q],+1), half2(W[e][32ks2+24+2q],+1) }
__device__ __align__(16) uint4 g_Wp[NE * 128 * 4];        // 512 KB
__device__ unsigned g_rtok[NTOK_MAX];                     // token | nc<<20
__device__ uint2    g_rcand[NTOK_MAX];                    // 8 packed candidate ids
__device__ int      g_count;

// ---------------- helpers ----------------
__device__ __forceinline__ unsigned f2h2(float a, float bb) {
    __half2 h = __float22half2_rn(make_float2(a, bb));
    return *(unsigned*)&h;
}
__device__ __forceinline__ void mma16816(float c[4], unsigned a0, unsigned a1,
                                         unsigned a2, unsigned a3,
                                         unsigned b0, unsigned b1) {
    asm volatile(
        "mma.sync.aligned.m16n8k16.row.col.f32.f16.f16.f32 "
        "{%0,%1,%2,%3}, {%4,%5,%6,%7}, {%8,%9}, {%0,%1,%2,%3};"
        : "+f"(c[0]), "+f"(c[1]), "+f"(c[2]), "+f"(c[3])
        : "r"(a0), "r"(a1), "r"(a2), "r"(a3), "r"(b0), "r"(b1));
}

// ================= K0: permute W fp32 -> warp-contiguous fragment fp16 =================
__global__ void k0_permute_w(const float* __restrict__ W) {
    if (blockIdx.x == 0 && threadIdx.x == 0) g_count = 0;
    int unit = blockIdx.x * blockDim.x + threadIdx.x;   // 0..8191 = (e, ks2)
    int e   = unit >> 7;
    int ks2 = unit & 127;
    int nt  = e >> 3;
    int rsub = e & 7;
    const float* src = W + (size_t)e * D_MODEL + ks2 * 32;

    float s[32];
    #pragma unroll
    for (int i = 0; i < 8; i++) {
        float4 v = *(const float4*)(src + i * 4);
        s[i * 4 + 0] = v.x; s[i * 4 + 1] = v.y; s[i * 4 + 2] = v.z; s[i * 4 + 3] = v.w;
    }
    uint4* dst = &g_Wp[((nt * 128 + ks2) * 8 + rsub) * 4];
    #pragma unroll
    for (int q = 0; q < 4; q++) {
        uint4 u;
        u.x = f2h2(s[2 * q],      s[2 * q + 1]);
        u.y = f2h2(s[8 + 2 * q],  s[8 + 2 * q + 1]);
        u.z = f2h2(s[16 + 2 * q], s[16 + 2 * q + 1]);
        u.w = f2h2(s[24 + 2 * q], s[24 + 2 * q + 1]);
        dst[q] = u;
    }
}

// ================= K1: fp16 MMA screen, 32 tokens/warp, 3 CTAs/SM =================
// CTA: 128 tokens, 4 warps; warp w -> tokens 32w..32w+31. (R12-proven geometry)
__global__ __launch_bounds__(128, 3)
void k1_screen(const float* __restrict__ X, const float* __restrict__ b,
               float* __restrict__ out, int n_tokens)
{
    __shared__ float sc[128 * 68];
    __shared__ float s_bias[NE];

    const int tid  = threadIdx.x;
    const int wid  = tid >> 5;               // 0..3
    const int lane = tid & 31;
    const int row0 = blockIdx.x * 128;
    const int q    = lane & 3;
    const int rsub = lane >> 2;              // 0..7
    const int srcA = (lane & ~3) | ((lane >> 1) & 1);   // base + (q>>1)
    const bool hiP = (lane & 1);

    if (tid < NE) s_bias[tid] = b[tid];

    // rows: block0 = {rsub, rsub+8}, block1 = {rsub+16, rsub+24} within 32w..32w+31
    const float* xr0  = X + (size_t)(row0 + 32 * wid + rsub) * D_MODEL + 4 * q;
    const float* xr8  = xr0 + (size_t)8  * D_MODEL;
    const float* xr16 = xr0 + (size_t)16 * D_MODEL;
    const float* xr24 = xr0 + (size_t)24 * D_MODEL;

    float acc0[8][4], acc1[8][4];
    #pragma unroll
    for (int nt = 0; nt < 8; nt++)
        #pragma unroll
        for (int j = 0; j < 4; j++) { acc0[nt][j] = 0.0f; acc1[nt][j] = 0.0f; }

    for (int ks2 = 0; ks2 < 128; ks2++) {
        const int k = ks2 * 32;
        // 8 independent A loads (evict-first X stream)
        float4 L0 = __ldcs((const float4*)(xr0  + k));
        float4 L1 = __ldcs((const float4*)(xr0  + k + 16));
        float4 L2 = __ldcs((const float4*)(xr8  + k));
        float4 L3 = __ldcs((const float4*)(xr8  + k + 16));
        float4 L4 = __ldcs((const float4*)(xr16 + k));
        float4 L5 = __ldcs((const float4*)(xr16 + k + 16));
        float4 L6 = __ldcs((const float4*)(xr24 + k));
        float4 L7 = __ldcs((const float4*)(xr24 + k + 16));

        // pack own pairs to half2 (R11-proven mapping per block)
        unsigned h00 = f2h2(L0.x, L0.y), h01 = f2h2(L0.z, L0.w);
        unsigned h10 = f2h2(L1.x, L1.y), h11 = f2h2(L1.z, L1.w);
        unsigned h20 = f2h2(L2.x, L2.y), h21 = f2h2(L2.z, L2.w);
        unsigned h30 = f2h2(L3.x, L3.y), h31 = f2h2(L3.z, L3.w);
        unsigned h40 = f2h2(L4.x, L4.y), h41 = f2h2(L4.z, L4.w);
        unsigned h50 = f2h2(L5.x, L5.y), h51 = f2h2(L5.z, L5.w);
        unsigned h60 = f2h2(L6.x, L6.y), h61 = f2h2(L6.z, L6.w);
        unsigned h70 = f2h2(L7.x, L7.y), h71 = f2h2(L7.z, L7.w);

        unsigned u0, u1;
        #define FRAG(hA, hB, off, dst) \
            u0 = __shfl_sync(0xFFFFFFFFu, hA, srcA + (off)); \
            u1 = __shfl_sync(0xFFFFFFFFu, hB, srcA + (off)); \
            unsigned dst = hiP ? u1 : u0;

        // block0 fragments (rows rsub, rsub+8)
        FRAG(h00, h01, 0, aE0)  FRAG(h20, h21, 0, aE1)
        FRAG(h00, h01, 2, aE2)  FRAG(h20, h21, 2, aE3)
        FRAG(h10, h11, 0, aO0)  FRAG(h30, h31, 0, aO1)
        FRAG(h10, h11, 2, aO2)  FRAG(h30, h31, 2, aO3)
        // block1 fragments (rows rsub+16, rsub+24)
        FRAG(h40, h41, 0, bE0)  FRAG(h60, h61, 0, bE1)
        FRAG(h40, h41, 2, bE2)  FRAG(h60, h61, 2, bE3)
        FRAG(h50, h51, 0, bO0)  FRAG(h70, h71, 0, bO1)
        FRAG(h50, h51, 2, bO2)  FRAG(h70, h71, 2, bO3)
        #undef FRAG

        #pragma unroll
        for (int nt = 0; nt < 8; nt++) {
            uint4 bb = __ldg(&g_Wp[((nt * 128 + ks2) * 8) * 4 + lane]);
            mma16816(acc0[nt], aE0, aE1, aE2, aE3, bb.x, bb.y);
            mma16816(acc0[nt], aO0, aO1, aO2, aO3, bb.z, bb.w);
            mma16816(acc1[nt], bE0, bE1, bE2, bE3, bb.x, bb.y);
            mma16816(acc1[nt], bO0, bO1, bO2, bO3, bb.z, bb.w);
        }
    }

    // ---- scores to smem ----
    {
        int r = 32 * wid + rsub;
        int cb = 2 * q;
        #pragma unroll
        for (int nt = 0; nt < 8; nt++) {
            int c = 8 * nt + cb;
            sc[r * 68 + c]              = acc0[nt][0];
            sc[r * 68 + c + 1]          = acc0[nt][1];
            sc[(r + 8) * 68 + c]        = acc0[nt][2];
            sc[(r + 8) * 68 + c + 1]    = acc0[nt][3];
            sc[(r + 16) * 68 + c]       = acc1[nt][0];
            sc[(r + 16) * 68 + c + 1]   = acc1[nt][1];
            sc[(r + 24) * 68 + c]       = acc1[nt][2];
            sc[(r + 24) * 68 + c + 1]   = acc1[nt][3];
        }
    }
    __syncthreads();

    // ---- per-token top-8 scan, certify, write outputs, rescue ----
    {
        float sv[8];
        int   si[8];
        #pragma unroll
        for (int j = 0; j < 8; j++) { sv[j] = -INFINITY; si[j] = 0; }
        #pragma unroll
        for (int e = 0; e < NE; e++) {
            float cs = sc[tid * 68 + e] + s_bias[e];
            int ci = e;
            #pragma unroll
            for (int j = 0; j < 8; j++) {
                if (cs > sv[j]) {
                    float tf = sv[j]; int ti = si[j];
                    sv[j] = cs; si[j] = ci; cs = tf; ci = ti;
                }
            }
        }
        int token = row0 + tid;

        float e2v = expf(sv[1] - sv[0]);
        float inv = 1.0f / (1.0f + e2v);
        out[(size_t)token * 2 + 0] = inv;
        out[(size_t)token * 2 + 1] = e2v * inv;
        size_t idx_base = (size_t)n_tokens * 2;
        out[idx_base + (size_t)token * 2 + 0] = (float)si[0];
        out[idx_base + (size_t)token * 2 + 1] = (float)si[1];

        if ((sv[0] - sv[1] < TAU) || (sv[1] - sv[2] < TAU)) {
            int nc = 2;
            float thr = sv[1] - WIN;
            #pragma unroll
            for (int j = 2; j < 8; j++)
                if (sv[j] >= thr) nc = j + 1;
            int slot = atomicAdd(&g_count, 1);
            g_rtok[slot] = (unsigned)token | ((unsigned)nc << 20);
            unsigned lo = (unsigned)si[0] | ((unsigned)si[1] << 8) |
                          ((unsigned)si[2] << 16) | ((unsigned)si[3] << 24);
            unsigned hi = (unsigned)si[4] | ((unsigned)si[5] << 8) |
                          ((unsigned)si[6] << 16) | ((unsigned)si[7] << 24);
            g_rcand[slot] = make_uint2(lo, hi);
        }
    }
}

// ================= K3: warp-per-token exact fp32 rescore of the candidate window =================
__global__ __launch_bounds__(256, 4)
void k3_rescue(const float* __restrict__ X, const float* __restrict__ W,
               const float* __restrict__ b, float* __restrict__ out, int n_tokens)
{
    const int lane   = threadIdx.x & 31;
    const int gw     = (blockIdx.x * blockDim.x + threadIdx.x) >> 5;
    const int nwarps = (gridDim.x * blockDim.x) >> 5;
    const int cnt    = g_count;

    for (int it = gw; it < cnt; it += nwarps) {
        unsigned tv = g_rtok[it];
        const int token = tv & 0xFFFFF;
        const int nc    = tv >> 20;
        uint2 cd = g_rcand[it];
        int e[8];
        #pragma unroll
        for (int j = 0; j < 4; j++) e[j]     = (cd.x >> (8 * j)) & 63;
        #pragma unroll
        for (int j = 0; j < 4; j++) e[4 + j] = (cd.y >> (8 * j)) & 63;

        const float* xrow = X + (size_t)token * D_MODEL;

        float sum[8], cmp[8];
        #pragma unroll
        for (int j = 0; j < 8; j++) { sum[j] = 0.0f; cmp[j] = 0.0f; }

        for (int st = 0; st < D_MODEL / 128; st++) {       // 32 steps
            float4 xq = *(const float4*)(xrow + st * 128 + lane * 4);
            #pragma unroll
            for (int j = 0; j < 8; j++) {
                if (j >= nc) break;                        // warp-uniform
                float4 wq = __ldg((const float4*)(W + (size_t)e[j] * D_MODEL
                                                    + st * 128 + lane * 4));
                float s = xq.x * wq.x;
                s = fmaf(xq.y, wq.y, s);
                s = fmaf(xq.z, wq.z, s);
                s = fmaf(xq.w, wq.w, s);
                float y  = __fsub_rn(s, cmp[j]);
                float s2 = __fadd_rn(sum[j], y);
                cmp[j] = __fsub_rn(__fsub_rn(s2, sum[j]), y);
                sum[j] = s2;
            }
        }

        float m1 = -INFINITY, m2 = -INFINITY;
        int   i1 = 0,         i2 = 0;
        #pragma unroll
        for (int j = 0; j < 8; j++) {
            if (j >= nc) break;
            float s = __fadd_rn(sum[j], __fsub_rn(0.0f, cmp[j]));
            s = __fadd_rn(s, __shfl_xor_sync(0xFFFFFFFFu, s, 1));
            s = __fadd_rn(s, __shfl_xor_sync(0xFFFFFFFFu, s, 2));
            s = __fadd_rn(s, __shfl_xor_sync(0xFFFFFFFFu, s, 4));
            s = __fadd_rn(s, __shfl_xor_sync(0xFFFFFFFFu, s, 8));
            s = __fadd_rn(s, __shfl_xor_sync(0xFFFFFFFFu, s, 16));
            s = __fadd_rn(s, b[e[j]]);
            if (s > m1 || (s == m1 && e[j] < i1)) {
                m2 = m1; i2 = i1; m1 = s; i1 = e[j];
            } else if (s > m2 || (s == m2 && e[j] < i2)) {
                m2 = s; i2 = e[j];
            }
        }

        if (lane == 0) {
            float e2v = expf(m2 - m1);
            float inv = 1.0f / (1.0f + e2v);
            out[(size_t)token * 2 + 0] = inv;
            out[(size_t)token * 2 + 1] = e2v * inv;
            size_t idx_base = (size_t)n_tokens * 2;
            out[idx_base + (size_t)token * 2 + 0] = (float)i1;
            out[idx_base + (size_t)token * 2 + 1] = (float)i2;
        }
    }
}

// ================= launch =================
extern "C" void kernel_launch(void* const* d_in, const int* in_sizes, int n_in,
                              void* d_out, int out_size)
{
    const float* X = (const float*)d_in[0];   // [N, 4096]
    const float* W = (const float*)d_in[1];   // [64, 4096]
    const float* b = (const float*)d_in[2];   // [64]
    float* out = (float*)d_out;

    int n_tokens = in_sizes[0] / D_MODEL;     // 32768

    k0_permute_w<<<32, 256>>>(W);
    k1_screen<<<n_tokens / 128, 128>>>(X, b, out, n_tokens);
    k3_rescue<<<296, 256>>>(X, W, b, out, n_tokens);
}

// round 15
// speedup vs baseline: 1.2478x; 1.2478x over previous
#include <cuda_runtime.h>
#include <cuda_fp16.h>
#include <math.h>
#include <stdint.h>

#define D_MODEL   4096
#define NE        64
#define NTOK_MAX  32768
#define TAU       5e-3f   // certification margin (~12.5 sigma of fp16 screen noise)
#define WIN       5e-3f   // candidate-containment window for rescued tokens

// ---------------- scratch (__device__ globals: allocation-free) ----------------
// W permuted into warp-contiguous HMMA B-fragment blocks (R11-proven layout):
// block (nt, ks2) = 512B; lane l = rsub*4+q (expert e = nt*8+rsub) holds uint4 =
//   { half2(W[e][32ks2+2q],+1), half2(W[e][32ks2+8+2q],+1),
//     half2(W[e][32ks2+16+2q],+1), half2(W[e][32ks2+24+2q],+1) }
__device__ __align__(16) uint4 g_Wp[NE * 128 * 4];        // 512 KB
__device__ unsigned g_rtok[NTOK_MAX];                     // token | nc<<20
__device__ uint2    g_rcand[NTOK_MAX];                    // 8 packed candidate ids
__device__ int      g_count;

// ---------------- helpers ----------------
__device__ __forceinline__ unsigned f2h2(float a, float bb) {
    __half2 h = __float22half2_rn(make_float2(a, bb));
    return *(unsigned*)&h;
}
__device__ __forceinline__ void mma16816(float c[4], unsigned a0, unsigned a1,
                                         unsigned a2, unsigned a3,
                                         unsigned b0, unsigned b1) {
    asm volatile(
        "mma.sync.aligned.m16n8k16.row.col.f32.f16.f16.f32 "
        "{%0,%1,%2,%3}, {%4,%5,%6,%7}, {%8,%9}, {%0,%1,%2,%3};"
        : "+f"(c[0]), "+f"(c[1]), "+f"(c[2]), "+f"(c[3])
        : "r"(a0), "r"(a1), "r"(a2), "r"(a3), "r"(b0), "r"(b1));
}

// ================= K0: permute W fp32 -> warp-contiguous fragment fp16 =================
__global__ void k0_permute_w(const float* __restrict__ W) {
    if (blockIdx.x == 0 && threadIdx.x == 0) g_count = 0;
    int unit = blockIdx.x * blockDim.x + threadIdx.x;   // 0..8191 = (e, ks2)
    int e   = unit >> 7;
    int ks2 = unit & 127;
    int nt  = e >> 3;
    int rsub = e & 7;
    const float* src = W + (size_t)e * D_MODEL + ks2 * 32;

    float s[32];
    #pragma unroll
    for (int i = 0; i < 8; i++) {
        float4 v = *(const float4*)(src + i * 4);
        s[i * 4 + 0] = v.x; s[i * 4 + 1] = v.y; s[i * 4 + 2] = v.z; s[i * 4 + 3] = v.w;
    }
    uint4* dst = &g_Wp[((nt * 128 + ks2) * 8 + rsub) * 4];
    #pragma unroll
    for (int q = 0; q < 4; q++) {
        uint4 u;
        u.x = f2h2(s[2 * q],      s[2 * q + 1]);
        u.y = f2h2(s[8 + 2 * q],  s[8 + 2 * q + 1]);
        u.z = f2h2(s[16 + 2 * q], s[16 + 2 * q + 1]);
        u.w = f2h2(s[24 + 2 * q], s[24 + 2 * q + 1]);
        dst[q] = u;
    }
}

// ================= K1: fp16 MMA screen, 32 tokens/warp (R12 config, unroll-2) =================
// CTA: 128 tokens, 4 warps; warp w -> tokens 32w..32w+31.
__global__ __launch_bounds__(128, 2)
void k1_screen(const float* __restrict__ X, const float* __restrict__ b,
               float* __restrict__ out, int n_tokens)
{
    __shared__ float sc[128 * 68];
    __shared__ float s_bias[NE];

    const int tid  = threadIdx.x;
    const int wid  = tid >> 5;               // 0..3
    const int lane = tid & 31;
    const int row0 = blockIdx.x * 128;
    const int q    = lane & 3;
    const int rsub = lane >> 2;              // 0..7
    const int srcA = (lane & ~3) | ((lane >> 1) & 1);   // base + (q>>1)
    const bool hiP = (lane & 1);

    if (tid < NE) s_bias[tid] = b[tid];

    // rows: block0 = {rsub, rsub+8}, block1 = {rsub+16, rsub+24} within 32w..32w+31
    const float* xr0  = X + (size_t)(row0 + 32 * wid + rsub) * D_MODEL + 4 * q;
    const float* xr8  = xr0 + (size_t)8  * D_MODEL;
    const float* xr16 = xr0 + (size_t)16 * D_MODEL;
    const float* xr24 = xr0 + (size_t)24 * D_MODEL;

    float acc0[8][4], acc1[8][4];
    #pragma unroll
    for (int nt = 0; nt < 8; nt++)
        #pragma unroll
        for (int j = 0; j < 4; j++) { acc0[nt][j] = 0.0f; acc1[nt][j] = 0.0f; }

    #pragma unroll 2
    for (int ks2 = 0; ks2 < 128; ks2++) {
        const int k = ks2 * 32;
        // 8 independent A loads (evict-first X stream)
        float4 L0 = __ldcs((const float4*)(xr0  + k));
        float4 L1 = __ldcs((const float4*)(xr0  + k + 16));
        float4 L2 = __ldcs((const float4*)(xr8  + k));
        float4 L3 = __ldcs((const float4*)(xr8  + k + 16));
        float4 L4 = __ldcs((const float4*)(xr16 + k));
        float4 L5 = __ldcs((const float4*)(xr16 + k + 16));
        float4 L6 = __ldcs((const float4*)(xr24 + k));
        float4 L7 = __ldcs((const float4*)(xr24 + k + 16));

        // pack own pairs to half2 (R11-proven mapping per block)
        unsigned h00 = f2h2(L0.x, L0.y), h01 = f2h2(L0.z, L0.w);
        unsigned h10 = f2h2(L1.x, L1.y), h11 = f2h2(L1.z, L1.w);
        unsigned h20 = f2h2(L2.x, L2.y), h21 = f2h2(L2.z, L2.w);
        unsigned h30 = f2h2(L3.x, L3.y), h31 = f2h2(L3.z, L3.w);
        unsigned h40 = f2h2(L4.x, L4.y), h41 = f2h2(L4.z, L4.w);
        unsigned h50 = f2h2(L5.x, L5.y), h51 = f2h2(L5.z, L5.w);
        unsigned h60 = f2h2(L6.x, L6.y), h61 = f2h2(L6.z, L6.w);
        unsigned h70 = f2h2(L7.x, L7.y), h71 = f2h2(L7.z, L7.w);

        unsigned u0, u1;
        #define FRAG(hA, hB, off, dst) \
            u0 = __shfl_sync(0xFFFFFFFFu, hA, srcA + (off)); \
            u1 = __shfl_sync(0xFFFFFFFFu, hB, srcA + (off)); \
            unsigned dst = hiP ? u1 : u0;

        // block0 fragments (rows rsub, rsub+8)
        FRAG(h00, h01, 0, aE0)  FRAG(h20, h21, 0, aE1)
        FRAG(h00, h01, 2, aE2)  FRAG(h20, h21, 2, aE3)
        FRAG(h10, h11, 0, aO0)  FRAG(h30, h31, 0, aO1)
        FRAG(h10, h11, 2, aO2)  FRAG(h30, h31, 2, aO3)
        // block1 fragments (rows rsub+16, rsub+24)
        FRAG(h40, h41, 0, bE0)  FRAG(h60, h61, 0, bE1)
        FRAG(h40, h41, 2, bE2)  FRAG(h60, h61, 2, bE3)
        FRAG(h50, h51, 0, bO0)  FRAG(h70, h71, 0, bO1)
        FRAG(h50, h51, 2, bO2)  FRAG(h70, h71, 2, bO3)
        #undef FRAG

        #pragma unroll
        for (int nt = 0; nt < 8; nt++) {
            uint4 bb = __ldg(&g_Wp[((nt * 128 + ks2) * 8) * 4 + lane]);
            mma16816(acc0[nt], aE0, aE1, aE2, aE3, bb.x, bb.y);
            mma16816(acc0[nt], aO0, aO1, aO2, aO3, bb.z, bb.w);
            mma16816(acc1[nt], bE0, bE1, bE2, bE3, bb.x, bb.y);
            mma16816(acc1[nt], bO0, bO1, bO2, bO3, bb.z, bb.w);
        }
    }

    // ---- scores to smem ----
    {
        int r = 32 * wid + rsub;
        int cb = 2 * q;
        #pragma unroll
        for (int nt = 0; nt < 8; nt++) {
            int c = 8 * nt + cb;
            sc[r * 68 + c]              = acc0[nt][0];
            sc[r * 68 + c + 1]          = acc0[nt][1];
            sc[(r + 8) * 68 + c]        = acc0[nt][2];
            sc[(r + 8) * 68 + c + 1]    = acc0[nt][3];
            sc[(r + 16) * 68 + c]       = acc1[nt][0];
            sc[(r + 16) * 68 + c + 1]   = acc1[nt][1];
            sc[(r + 24) * 68 + c]       = acc1[nt][2];
            sc[(r + 24) * 68 + c + 1]   = acc1[nt][3];
        }
    }
    __syncthreads();

    // ---- per-token top-8 scan, certify, write outputs, rescue ----
    {
        float sv[8];
        int   si[8];
        #pragma unroll
        for (int j = 0; j < 8; j++) { sv[j] = -INFINITY; si[j] = 0; }
        #pragma unroll
        for (int e = 0; e < NE; e++) {
            float cs = sc[tid * 68 + e] + s_bias[e];
            int ci = e;
            #pragma unroll
            for (int j = 0; j < 8; j++) {
                if (cs > sv[j]) {
                    float tf = sv[j]; int ti = si[j];
                    sv[j] = cs; si[j] = ci; cs = tf; ci = ti;
                }
            }
        }
        int token = row0 + tid;

        float e2v = expf(sv[1] - sv[0]);
        float inv = 1.0f / (1.0f + e2v);
        out[(size_t)token * 2 + 0] = inv;
        out[(size_t)token * 2 + 1] = e2v * inv;
        size_t idx_base = (size_t)n_tokens * 2;
        out[idx_base + (size_t)token * 2 + 0] = (float)si[0];
        out[idx_base + (size_t)token * 2 + 1] = (float)si[1];

        if ((sv[0] - sv[1] < TAU) || (sv[1] - sv[2] < TAU)) {
            int nc = 2;
            float thr = sv[1] - WIN;
            #pragma unroll
            for (int j = 2; j < 8; j++)
                if (sv[j] >= thr) nc = j + 1;
            int slot = atomicAdd(&g_count, 1);
            g_rtok[slot] = (unsigned)token | ((unsigned)nc << 20);
            unsigned lo = (unsigned)si[0] | ((unsigned)si[1] << 8) |
                          ((unsigned)si[2] << 16) | ((unsigned)si[3] << 24);
            unsigned hi = (unsigned)si[4] | ((unsigned)si[5] << 8) |
                          ((unsigned)si[6] << 16) | ((unsigned)si[7] << 24);
            g_rcand[slot] = make_uint2(lo, hi);
        }
    }
}

// ================= K3: warp-per-token exact fp32 rescore of the candidate window =================
__global__ __launch_bounds__(256, 4)
void k3_rescue(const float* __restrict__ X, const float* __restrict__ W,
               const float* __restrict__ b, float* __restrict__ out, int n_tokens)
{
    const int lane   = threadIdx.x & 31;
    const int gw     = (blockIdx.x * blockDim.x + threadIdx.x) >> 5;
    const int nwarps = (gridDim.x * blockDim.x) >> 5;
    const int cnt    = g_count;

    for (int it = gw; it < cnt; it += nwarps) {
        unsigned tv = g_rtok[it];
        const int token = tv & 0xFFFFF;
        const int nc    = tv >> 20;
        uint2 cd = g_rcand[it];
        int e[8];
        #pragma unroll
        for (int j = 0; j < 4; j++) e[j]     = (cd.x >> (8 * j)) & 63;
        #pragma unroll
        for (int j = 0; j < 4; j++) e[4 + j] = (cd.y >> (8 * j)) & 63;

        const float* xrow = X + (size_t)token * D_MODEL;

        float sum[8], cmp[8];
        #pragma unroll
        for (int j = 0; j < 8; j++) { sum[j] = 0.0f; cmp[j] = 0.0f; }

        for (int st = 0; st < D_MODEL / 128; st++) {       // 32 steps
            float4 xq = *(const float4*)(xrow + st * 128 + lane * 4);
            #pragma unroll
            for (int j = 0; j < 8; j++) {
                if (j >= nc) break;                        // warp-uniform
                float4 wq = __ldg((const float4*)(W + (size_t)e[j] * D_MODEL
                                                    + st * 128 + lane * 4));
                float s = xq.x * wq.x;
                s = fmaf(xq.y, wq.y, s);
                s = fmaf(xq.z, wq.z, s);
                s = fmaf(xq.w, wq.w, s);
                float y  = __fsub_rn(s, cmp[j]);
                float s2 = __fadd_rn(sum[j], y);
                cmp[j] = __fsub_rn(__fsub_rn(s2, sum[j]), y);
                sum[j] = s2;
            }
        }

        float m1 = -INFINITY, m2 = -INFINITY;
        int   i1 = 0,         i2 = 0;
        #pragma unroll
        for (int j = 0; j < 8; j++) {
            if (j >= nc) break;
            float s = __fadd_rn(sum[j], __fsub_rn(0.0f, cmp[j]));
            s = __fadd_rn(s, __shfl_xor_sync(0xFFFFFFFFu, s, 1));
            s = __fadd_rn(s, __shfl_xor_sync(0xFFFFFFFFu, s, 2));
            s = __fadd_rn(s, __shfl_xor_sync(0xFFFFFFFFu, s, 4));
            s = __fadd_rn(s, __shfl_xor_sync(0xFFFFFFFFu, s, 8));
            s = __fadd_rn(s, __shfl_xor_sync(0xFFFFFFFFu, s, 16));
            s = __fadd_rn(s, b[e[j]]);
            if (s > m1 || (s == m1 && e[j] < i1)) {
                m2 = m1; i2 = i1; m1 = s; i1 = e[j];
            } else if (s > m2 || (s == m2 && e[j] < i2)) {
                m2 = s; i2 = e[j];
            }
        }

        if (lane == 0) {
            float e2v = expf(m2 - m1);
            float inv = 1.0f / (1.0f + e2v);
            out[(size_t)token * 2 + 0] = inv;
            out[(size_t)token * 2 + 1] = e2v * inv;
            size_t idx_base = (size_t)n_tokens * 2;
            out[idx_base + (size_t)token * 2 + 0] = (float)i1;
            out[idx_base + (size_t)token * 2 + 1] = (float)i2;
        }
    }
}

// ================= launch =================
extern "C" void kernel_launch(void* const* d_in, const int* in_sizes, int n_in,
                              void* d_out, int out_size)
{
    const float* X = (const float*)d_in[0];   // [N, 4096]
    const float* W = (const float*)d_in[1];   // [64, 4096]
    const float* b = (const float*)d_in[2];   // [64]
    float* out = (float*)d_out;

    int n_tokens = in_sizes[0] / D_MODEL;     // 32768

    k0_permute_w<<<32, 256>>>(W);
    k1_screen<<<n_tokens / 128, 128>>>(X, b, out, n_tokens);
    k3_rescue<<<296, 256>>>(X, W, b, out, n_tokens);
}